// round 3
// baseline (speedup 1.0000x reference)
#include <cuda_runtime.h>
#include <math.h>

#define HH 256
#define WW 256
#define HW (HH*WW)

// ---------------- scratch (static device globals; no allocs) ----------------
__device__ float g_t1[64 * HW];
__device__ float g_t2[64 * HW];
__device__ float g_off[216 * HW];     // raw offset-branch conv4 output
__device__ float g_cat[128 * HW];     // concat(fp, fn) for fusion conv

typedef unsigned long long ull;

// packed f32x2 helpers (sm_100+ PTX)
__device__ __forceinline__ ull pk2(float v) {
    ull r; asm("mov.b64 %0, {%1, %1};" : "=l"(r) : "f"(v)); return r;
}
__device__ __forceinline__ ull ffma2(ull a, ull b, ull c) {
    ull r; asm("fma.rn.f32x2 %0, %1, %2, %3;" : "=l"(r) : "l"(a), "l"(b), "l"(c)); return r;
}
__device__ __forceinline__ void unpk2(ull v, float& lo, float& hi) {
    asm("mov.b64 {%0, %1}, %2;" : "=f"(lo), "=f"(hi) : "l"(v));
}

// ---------------- conv3x3, pad 1, stride 1 (FFMA2 over oc pairs) ----------------
// Persistent blocks. Block: 256 threads = 16(tx) x 16(ty).
// Tile: 64 wide x 16 high; thread owns px {tx, tx+16, tx+32, tx+48} (stride-1 LDS).
// 8 output channels per tile (4 f32x2 pairs). Cin in chunks of 8.
template<bool LRELU>
__global__ __launch_bounds__(256, 3)
void conv3x3_kernel(const float* __restrict__ in,
                    const float* __restrict__ w,
                    const float* __restrict__ bias,
                    float* __restrict__ out,
                    int Cin, int Cout, int ntiles) {
    __shared__ float s_in[8][18][67];
    __shared__ __align__(8) float s_w[8][9][8];   // [c][tap][oc]

    const int tid = threadIdx.x;
    const int tx = tid & 15, ty = tid >> 4;

    for (int t = blockIdx.x; t < ntiles; t += gridDim.x) {
        const int zi = t >> 6;            // 64 = 4x16 spatial tiles per oc-block
        const int rem = t & 63;
        const int yt = rem >> 2, xt = rem & 3;
        const int x0 = xt * 64, y0 = yt * 16;
        const int ocb = zi * 8;

        ull acc[4][4];
#pragma unroll
        for (int p = 0; p < 4; p++)
#pragma unroll
            for (int q = 0; q < 4; q++) acc[p][q] = 0ULL;

        for (int c0 = 0; c0 < Cin; c0 += 8) {
            __syncthreads();   // protect smem from previous compute/tile
            // input tile: 8ch x 18 rows x 66 cols
            for (int i = tid; i < 8 * 18 * 66; i += 256) {
                int c = i / (18 * 66);
                int rem2 = i % (18 * 66);
                int r = rem2 / 66, col = rem2 % 66;
                int gy = y0 + r - 1, gx = x0 + col - 1;
                float v = 0.f;
                if (gy >= 0 && gy < HH && gx >= 0 && gx < WW)
                    v = in[(c0 + c) * HW + gy * WW + gx];
                s_in[c][r][col] = v;
            }
            // weights: 8 oc x 8 c x 9 taps
            for (int i = tid; i < 8 * 9 * 8; i += 256) {
                int oc = i & 7, tap = (i >> 3) % 9, c = i / 72;
                s_w[c][tap][oc] = w[((ocb + oc) * Cin + (c0 + c)) * 9 + tap];
            }
            __syncthreads();

#pragma unroll
            for (int c = 0; c < 8; c++) {
#pragma unroll
                for (int ky = 0; ky < 3; ky++) {
                    ull vin[4][3];
#pragma unroll
                    for (int q = 0; q < 4; q++)
#pragma unroll
                        for (int kx = 0; kx < 3; kx++)
                            vin[q][kx] = pk2(s_in[c][ty + ky][tx + 16 * q + kx]);
#pragma unroll
                    for (int kx = 0; kx < 3; kx++) {
#pragma unroll
                        for (int p = 0; p < 4; p++) {
                            ull wp = *reinterpret_cast<const ull*>(&s_w[c][ky * 3 + kx][2 * p]);
                            acc[p][0] = ffma2(vin[0][kx], wp, acc[p][0]);
                            acc[p][1] = ffma2(vin[1][kx], wp, acc[p][1]);
                            acc[p][2] = ffma2(vin[2][kx], wp, acc[p][2]);
                            acc[p][3] = ffma2(vin[3][kx], wp, acc[p][3]);
                        }
                    }
                }
            }
        }

        const int y = y0 + ty;
#pragma unroll
        for (int p = 0; p < 4; p++) {
            int oc0 = ocb + 2 * p, oc1 = oc0 + 1;
            float bv0 = bias[oc0], bv1 = bias[oc1];
            float lo, hi;
#pragma unroll
            for (int q = 0; q < 4; q++) {
                unpk2(acc[p][q], lo, hi);
                float r0 = lo + bv0, r1 = hi + bv1;
                if (LRELU) {
                    r0 = r0 >= 0.f ? r0 : 0.1f * r0;
                    r1 = r1 >= 0.f ? r1 : 0.1f * r1;
                }
                out[oc0 * HW + y * WW + x0 + tx + 16 * q] = r0;
                out[oc1 * HW + y * WW + x0 + tx + 16 * q] = r1;
            }
        }
    }
}

// ---------------- fused deformable gather + grouped GEMM ----------------
// out[oc][px] = sum_{g,c,k} w[oc][g*72+c*9+k] * bilinear(feat[g*8+c]) * mask + b
// Block: 256 threads, 1 px/thread, all 64 oc (32 f32x2 pairs) per block.
__global__ __launch_bounds__(256, 2)
void dcn_fused_kernel(const float* __restrict__ feat,
                      const float* __restrict__ offraw,
                      const float* __restrict__ flow,
                      const float* __restrict__ w,
                      const float* __restrict__ bias,
                      float* __restrict__ out) {
    __shared__ __align__(8) float s_w[72][64];   // [c*9+k][oc]

    const int tid = threadIdx.x;
    const int px = blockIdx.x * 256 + tid;
    const int y = px >> 8, x = px & 255;

    const float fly = flow[HW + px], flx = flow[px];

    ull acc[32];
#pragma unroll
    for (int p = 0; p < 32; p++) acc[p] = 0ULL;

    for (int g = 0; g < 8; g++) {
        __syncthreads();
        for (int i = tid; i < 72 * 64; i += 256) {
            int oc = i & 63, ck = i >> 6;
            s_w[ck][oc] = w[oc * 576 + g * 72 + ck];
        }
        __syncthreads();

        const float* fg = feat + g * 8 * HW;

#pragma unroll
        for (int k = 0; k < 9; k++) {
            const int gk = g * 9 + k;
            float oy = 10.f * tanhf(offraw[(gk * 2 + 0) * HW + px]) + fly;
            float ox = 10.f * tanhf(offraw[(gk * 2 + 1) * HW + px]) + flx;
            float m = 1.f / (1.f + expf(-offraw[(144 + gk) * HW + px]));

            float py = (float)y + (float)(k / 3 - 1) + oy;
            float pxx = (float)x + (float)(k % 3 - 1) + ox;
            float y0f = floorf(py), x0f = floorf(pxx);
            float ly = py - y0f, lx = pxx - x0f;
            int yi0 = (int)y0f, xi0 = (int)x0f;
            int yi1 = yi0 + 1, xi1 = xi0 + 1;
            float vy0 = (yi0 >= 0 && yi0 < HH) ? 1.f : 0.f;
            float vy1 = (yi1 >= 0 && yi1 < HH) ? 1.f : 0.f;
            float vx0 = (xi0 >= 0 && xi0 < WW) ? 1.f : 0.f;
            float vx1 = (xi1 >= 0 && xi1 < WW) ? 1.f : 0.f;
            int yc0 = min(max(yi0, 0), HH - 1), yc1 = min(max(yi1, 0), HH - 1);
            int xc0 = min(max(xi0, 0), WW - 1), xc1 = min(max(xi1, 0), WW - 1);
            float w00 = (1.f - ly) * (1.f - lx) * vy0 * vx0 * m;
            float w01 = (1.f - ly) * lx * vy0 * vx1 * m;
            float w10 = ly * (1.f - lx) * vy1 * vx0 * m;
            float w11 = ly * lx * vy1 * vx1 * m;
            int i00 = yc0 * WW + xc0, i01 = yc0 * WW + xc1;
            int i10 = yc1 * WW + xc0, i11 = yc1 * WW + xc1;

#pragma unroll
            for (int c = 0; c < 8; c++) {
                const float* fc = fg + c * HW;
                float v = w00 * fc[i00] + w01 * fc[i01] + w10 * fc[i10] + w11 * fc[i11];
                ull sv = pk2(v);
                const int row = c * 9 + k;
#pragma unroll
                for (int p = 0; p < 32; p++) {
                    ull wp = *reinterpret_cast<const ull*>(&s_w[row][2 * p]);
                    acc[p] = ffma2(sv, wp, acc[p]);
                }
            }
        }
    }

#pragma unroll
    for (int p = 0; p < 32; p++) {
        int oc0 = 2 * p, oc1 = oc0 + 1;
        float a0, a1;
        unpk2(acc[p], a0, a1);
        out[oc0 * HW + px] = a0 + bias[oc0];
        out[oc1 * HW + px] = a1 + bias[oc1];
    }
}

// ---------------- host launch ----------------
#define CONV_GRID 444

static void run_branch(const float* feat, const float* extra, const float* flow,
                       const float* w0, const float* b0,
                       const float* w1, const float* b1,
                       const float* w2, const float* b2,
                       const float* w3, const float* b3,
                       const float* dw, const float* db,
                       float* t1, float* t2, float* off, float* branch_out) {
    dim3 blk(256);
    const int tiles64 = 64 * (64 / 8);       // 512
    const int tiles216 = 64 * (216 / 8);     // 1728

    conv3x3_kernel<true ><<<CONV_GRID, blk>>>(extra, w0, b0, t1, 128, 64, tiles64);
    conv3x3_kernel<true ><<<CONV_GRID, blk>>>(t1,    w1, b1, t2,  64, 64, tiles64);
    conv3x3_kernel<true ><<<CONV_GRID, blk>>>(t2,    w2, b2, t1,  64, 64, tiles64);
    conv3x3_kernel<false><<<CONV_GRID, blk>>>(t1,    w3, b3, off, 64, 216, tiles216);

    dcn_fused_kernel<<<HW / 256, blk>>>(feat, off, flow, dw, db, branch_out);
}

extern "C" void kernel_launch(void* const* d_in, const int* in_sizes, int n_in,
                              void* d_out, int out_size) {
    const float* feat_prev  = (const float*)d_in[0];
    const float* feat_next  = (const float*)d_in[1];
    const float* extra_prev = (const float*)d_in[2];
    const float* extra_next = (const float*)d_in[3];
    const float* flow_prev  = (const float*)d_in[4];
    const float* flow_next  = (const float*)d_in[5];
    const float* dcn1_w = (const float*)d_in[22];
    const float* dcn1_b = (const float*)d_in[23];
    const float* dcn2_w = (const float*)d_in[24];
    const float* dcn2_b = (const float*)d_in[25];
    const float* fus_w  = (const float*)d_in[26];
    const float* fus_b  = (const float*)d_in[27];

    float *t1, *t2, *off, *cat;
    cudaGetSymbolAddress((void**)&t1,  g_t1);
    cudaGetSymbolAddress((void**)&t2,  g_t2);
    cudaGetSymbolAddress((void**)&off, g_off);
    cudaGetSymbolAddress((void**)&cat, g_cat);

    run_branch(feat_prev, extra_prev, flow_prev,
               (const float*)d_in[6],  (const float*)d_in[7],
               (const float*)d_in[8],  (const float*)d_in[9],
               (const float*)d_in[10], (const float*)d_in[11],
               (const float*)d_in[12], (const float*)d_in[13],
               dcn1_w, dcn1_b, t1, t2, off, cat);

    run_branch(feat_next, extra_next, flow_next,
               (const float*)d_in[14], (const float*)d_in[15],
               (const float*)d_in[16], (const float*)d_in[17],
               (const float*)d_in[18], (const float*)d_in[19],
               (const float*)d_in[20], (const float*)d_in[21],
               dcn2_w, dcn2_b, t1, t2, off, cat + 64 * HW);

    dim3 blk(256);
    conv3x3_kernel<false><<<CONV_GRID, blk>>>(cat, fus_w, fus_b, (float*)d_out,
                                              128, 64, 64 * (64 / 8));
}

// round 4
// speedup vs baseline: 1.1247x; 1.1247x over previous
#include <cuda_runtime.h>
#include <math.h>

#define HH 256
#define WW 256
#define HW (HH*WW)

// ---------------- scratch (static device globals; no allocs) ----------------
__device__ float g_t1[64 * HW];
__device__ float g_t2[64 * HW];
__device__ float g_off[216 * HW];     // raw offset-branch conv4 output
__device__ float g_cat[128 * HW];     // concat(fp, fn) for fusion conv

typedef unsigned long long ull;

// packed f32x2 helpers (sm_100+ PTX)
__device__ __forceinline__ ull pk2(float v) {
    ull r; asm("mov.b64 %0, {%1, %1};" : "=l"(r) : "f"(v)); return r;
}
__device__ __forceinline__ ull ffma2(ull a, ull b, ull c) {
    ull r; asm("fma.rn.f32x2 %0, %1, %2, %3;" : "=l"(r) : "l"(a), "l"(b), "l"(c)); return r;
}
__device__ __forceinline__ void unpk2(ull v, float& lo, float& hi) {
    asm("mov.b64 {%0, %1}, %2;" : "=f"(lo), "=f"(hi) : "l"(v));
}

// ---------------- conv3x3, pad 1, stride 1 (FFMA2 over oc pairs) ----------------
// Persistent blocks. Block: 256 threads = 16(tx) x 16(ty).
// Tile: 32 wide x 16 high; thread owns px {tx, tx+16} (stride-1 LDS, conflict-free
// because smem row stride 48 == 16 mod 32 puts the two halves on disjoint banks).
// 16 output channels per tile (8 f32x2 pairs). Cin in chunks of 8.
template<bool LRELU>
__global__ __launch_bounds__(256, 3)
void conv3x3_kernel(const float* __restrict__ in,
                    const float* __restrict__ w,
                    const float* __restrict__ bias,
                    float* __restrict__ out,
                    int Cin, int Cout, int ntiles) {
    __shared__ float s_in[8][18][48];
    __shared__ __align__(8) float s_w[8][9][16];   // [c][tap][oc]

    const int tid = threadIdx.x;
    const int tx = tid & 15, ty = tid >> 4;

    for (int t = blockIdx.x; t < ntiles; t += gridDim.x) {
        const int sp = t & 127;            // 8 x-tiles * 16 y-tiles
        const int ocb = (t >> 7) * 16;
        const int xt = sp & 7, yt = sp >> 3;
        const int x0 = xt * 32, y0 = yt * 16;

        ull acc[8][2];
#pragma unroll
        for (int p = 0; p < 8; p++) { acc[p][0] = 0ULL; acc[p][1] = 0ULL; }

        for (int c0 = 0; c0 < Cin; c0 += 8) {
            __syncthreads();   // protect smem from previous compute
            // input tile: 8ch x 18 rows x 34 cols (row stride 48)
            for (int i = tid; i < 8 * 18 * 34; i += 256) {
                int c = i / (18 * 34);
                int rem = i % (18 * 34);
                int r = rem / 34, col = rem % 34;
                int gy = y0 + r - 1, gx = x0 + col - 1;
                float v = 0.f;
                if (gy >= 0 && gy < HH && gx >= 0 && gx < WW)
                    v = in[(c0 + c) * HW + gy * WW + gx];
                s_in[c][r][col] = v;
            }
            // weights: 16 oc x 8 c x 9 taps (zero-padded past Cout)
            for (int i = tid; i < 8 * 9 * 16; i += 256) {
                int oc = i & 15, tap = (i >> 4) % 9, c = i / 144;
                float v = 0.f;
                if (ocb + oc < Cout)
                    v = w[((ocb + oc) * Cin + (c0 + c)) * 9 + tap];
                s_w[c][tap][oc] = v;
            }
            __syncthreads();

#pragma unroll
            for (int c = 0; c < 8; c++) {
#pragma unroll
                for (int ky = 0; ky < 3; ky++) {
                    ull vin[2][3];
#pragma unroll
                    for (int q = 0; q < 2; q++)
#pragma unroll
                        for (int kx = 0; kx < 3; kx++)
                            vin[q][kx] = pk2(s_in[c][ty + ky][tx + 16 * q + kx]);
#pragma unroll
                    for (int kx = 0; kx < 3; kx++) {
#pragma unroll
                        for (int p = 0; p < 8; p++) {
                            ull wp = *reinterpret_cast<const ull*>(&s_w[c][ky * 3 + kx][2 * p]);
                            acc[p][0] = ffma2(vin[0][kx], wp, acc[p][0]);
                            acc[p][1] = ffma2(vin[1][kx], wp, acc[p][1]);
                        }
                    }
                }
            }
        }

        const int y = y0 + ty;
#pragma unroll
        for (int p = 0; p < 8; p++) {
            int oc0 = ocb + 2 * p, oc1 = oc0 + 1;
            float lo, hi;
            if (oc0 < Cout) {
                float bv0 = bias[oc0];
#pragma unroll
                for (int q = 0; q < 2; q++) {
                    unpk2(acc[p][q], lo, hi);
                    float r0 = lo + bv0;
                    if (LRELU) r0 = r0 >= 0.f ? r0 : 0.1f * r0;
                    out[oc0 * HW + y * WW + x0 + tx + 16 * q] = r0;
                }
            }
            if (oc1 < Cout) {
                float bv1 = bias[oc1];
#pragma unroll
                for (int q = 0; q < 2; q++) {
                    unpk2(acc[p][q], lo, hi);
                    float r1 = hi + bv1;
                    if (LRELU) r1 = r1 >= 0.f ? r1 : 0.1f * r1;
                    out[oc1 * HW + y * WW + x0 + tx + 16 * q] = r1;
                }
            }
        }
    }
}

// ---------------- fused deformable gather + grouped GEMM ----------------
// out[oc][px] = sum_{g,c,k} w[oc][g*72+c*9+k] * bilinear(feat[g*8+c]) * mask + b
// Block: 256 threads, 1 px/thread, all 64 oc (32 f32x2 pairs) per block.
__global__ __launch_bounds__(256, 2)
void dcn_fused_kernel(const float* __restrict__ feat,
                      const float* __restrict__ offraw,
                      const float* __restrict__ flow,
                      const float* __restrict__ w,
                      const float* __restrict__ bias,
                      float* __restrict__ out) {
    __shared__ __align__(8) float s_w[72][64];   // [c*9+k][oc]

    const int tid = threadIdx.x;
    const int px = blockIdx.x * 256 + tid;
    const int y = px >> 8, x = px & 255;

    const float fly = flow[HW + px], flx = flow[px];

    ull acc[32];
#pragma unroll
    for (int p = 0; p < 32; p++) acc[p] = 0ULL;

    for (int g = 0; g < 8; g++) {
        __syncthreads();
        for (int i = tid; i < 72 * 64; i += 256) {
            int oc = i & 63, ck = i >> 6;
            s_w[ck][oc] = w[oc * 576 + g * 72 + ck];
        }
        __syncthreads();

        const float* fg = feat + g * 8 * HW;

#pragma unroll
        for (int k = 0; k < 9; k++) {
            const int gk = g * 9 + k;
            float oy = 10.f * tanhf(offraw[(gk * 2 + 0) * HW + px]) + fly;
            float ox = 10.f * tanhf(offraw[(gk * 2 + 1) * HW + px]) + flx;
            float m = 1.f / (1.f + expf(-offraw[(144 + gk) * HW + px]));

            float py = (float)y + (float)(k / 3 - 1) + oy;
            float pxx = (float)x + (float)(k % 3 - 1) + ox;
            float y0f = floorf(py), x0f = floorf(pxx);
            float ly = py - y0f, lx = pxx - x0f;
            int yi0 = (int)y0f, xi0 = (int)x0f;
            int yi1 = yi0 + 1, xi1 = xi0 + 1;
            float vy0 = (yi0 >= 0 && yi0 < HH) ? 1.f : 0.f;
            float vy1 = (yi1 >= 0 && yi1 < HH) ? 1.f : 0.f;
            float vx0 = (xi0 >= 0 && xi0 < WW) ? 1.f : 0.f;
            float vx1 = (xi1 >= 0 && xi1 < WW) ? 1.f : 0.f;
            int yc0 = min(max(yi0, 0), HH - 1), yc1 = min(max(yi1, 0), HH - 1);
            int xc0 = min(max(xi0, 0), WW - 1), xc1 = min(max(xi1, 0), WW - 1);
            float w00 = (1.f - ly) * (1.f - lx) * vy0 * vx0 * m;
            float w01 = (1.f - ly) * lx * vy0 * vx1 * m;
            float w10 = ly * (1.f - lx) * vy1 * vx0 * m;
            float w11 = ly * lx * vy1 * vx1 * m;
            int i00 = yc0 * WW + xc0, i01 = yc0 * WW + xc1;
            int i10 = yc1 * WW + xc0, i11 = yc1 * WW + xc1;

#pragma unroll
            for (int c = 0; c < 8; c++) {
                const float* fc = fg + c * HW;
                float v = w00 * fc[i00] + w01 * fc[i01] + w10 * fc[i10] + w11 * fc[i11];
                ull sv = pk2(v);
                const int row = c * 9 + k;
#pragma unroll
                for (int p = 0; p < 32; p++) {
                    ull wp = *reinterpret_cast<const ull*>(&s_w[row][2 * p]);
                    acc[p] = ffma2(sv, wp, acc[p]);
                }
            }
        }
    }

#pragma unroll
    for (int p = 0; p < 32; p++) {
        int oc0 = 2 * p, oc1 = oc0 + 1;
        float a0, a1;
        unpk2(acc[p], a0, a1);
        out[oc0 * HW + px] = a0 + bias[oc0];
        out[oc1 * HW + px] = a1 + bias[oc1];
    }
}

// ---------------- host launch ----------------
#define CONV_GRID 444

static void run_branch(const float* feat, const float* extra, const float* flow,
                       const float* w0, const float* b0,
                       const float* w1, const float* b1,
                       const float* w2, const float* b2,
                       const float* w3, const float* b3,
                       const float* dw, const float* db,
                       float* t1, float* t2, float* off, float* branch_out) {
    dim3 blk(256);
    const int tiles64 = 128 * 4;             // 4 oc-blocks of 16
    const int tiles216 = 128 * 14;           // 14 oc-blocks (last half-masked)

    conv3x3_kernel<true ><<<CONV_GRID, blk>>>(extra, w0, b0, t1, 128, 64, tiles64);
    conv3x3_kernel<true ><<<CONV_GRID, blk>>>(t1,    w1, b1, t2,  64, 64, tiles64);
    conv3x3_kernel<true ><<<CONV_GRID, blk>>>(t2,    w2, b2, t1,  64, 64, tiles64);
    conv3x3_kernel<false><<<CONV_GRID, blk>>>(t1,    w3, b3, off, 64, 216, tiles216);

    dcn_fused_kernel<<<HW / 256, blk>>>(feat, off, flow, dw, db, branch_out);
}

extern "C" void kernel_launch(void* const* d_in, const int* in_sizes, int n_in,
                              void* d_out, int out_size) {
    const float* feat_prev  = (const float*)d_in[0];
    const float* feat_next  = (const float*)d_in[1];
    const float* extra_prev = (const float*)d_in[2];
    const float* extra_next = (const float*)d_in[3];
    const float* flow_prev  = (const float*)d_in[4];
    const float* flow_next  = (const float*)d_in[5];
    const float* dcn1_w = (const float*)d_in[22];
    const float* dcn1_b = (const float*)d_in[23];
    const float* dcn2_w = (const float*)d_in[24];
    const float* dcn2_b = (const float*)d_in[25];
    const float* fus_w  = (const float*)d_in[26];
    const float* fus_b  = (const float*)d_in[27];

    float *t1, *t2, *off, *cat;
    cudaGetSymbolAddress((void**)&t1,  g_t1);
    cudaGetSymbolAddress((void**)&t2,  g_t2);
    cudaGetSymbolAddress((void**)&off, g_off);
    cudaGetSymbolAddress((void**)&cat, g_cat);

    run_branch(feat_prev, extra_prev, flow_prev,
               (const float*)d_in[6],  (const float*)d_in[7],
               (const float*)d_in[8],  (const float*)d_in[9],
               (const float*)d_in[10], (const float*)d_in[11],
               (const float*)d_in[12], (const float*)d_in[13],
               dcn1_w, dcn1_b, t1, t2, off, cat);

    run_branch(feat_next, extra_next, flow_next,
               (const float*)d_in[14], (const float*)d_in[15],
               (const float*)d_in[16], (const float*)d_in[17],
               (const float*)d_in[18], (const float*)d_in[19],
               (const float*)d_in[20], (const float*)d_in[21],
               dcn2_w, dcn2_b, t1, t2, off, cat + 64 * HW);

    dim3 blk(256);
    conv3x3_kernel<false><<<CONV_GRID, blk>>>(cat, fus_w, fus_b, (float*)d_out,
                                              128, 64, 128 * 4);
}

// round 5
// speedup vs baseline: 1.4061x; 1.2502x over previous
#include <cuda_runtime.h>
#include <cuda_bf16.h>
#include <math.h>

#define HH 256
#define WW 256
#define HW (HH*WW)

typedef unsigned int uint;
typedef unsigned long long ull;

// ---------------- scratch (static device globals; no allocs) ----------------
__device__ float g_t1[64 * HW];
__device__ float g_t2[64 * HW];
__device__ float g_off[216 * HW];
__device__ float g_cat[128 * HW];

// pre-converted bf16 hi/lo weights, layout [tap][OCPAD][Cin] per layer
// off1: L0@0(73728) L1@73728(36864) L2@110592(36864) L3@147456(147456)
// off2: +294912 ; fus: @589824(73728) ; total 663552
__device__ __align__(16) __nv_bfloat16 g_whi[663552];
__device__ __align__(16) __nv_bfloat16 g_wlo[663552];

// ---------------- weight pre-convert ----------------
__global__ void wconv_kernel(const float* __restrict__ w,
                             __nv_bfloat16* __restrict__ dhi,
                             __nv_bfloat16* __restrict__ dlo,
                             int Cout, int Cin, int OCPAD) {
    int i = blockIdx.x * 256 + threadIdx.x;
    int total = 9 * OCPAD * Cin;
    if (i >= total) return;
    int c = i % Cin;
    int rem = i / Cin;
    int oc = rem % OCPAD;
    int tap = rem / OCPAD;
    float v = 0.f;
    if (oc < Cout) v = w[(oc * Cin + c) * 9 + tap];
    __nv_bfloat16 hi = __float2bfloat16(v);
    float r = v - __bfloat162float(hi);
    dhi[i] = hi;
    dlo[i] = __float2bfloat16(r);
}

// ---------------- mma helpers ----------------
__device__ __forceinline__ void ldsm_x4(uint& r0, uint& r1, uint& r2, uint& r3, uint addr) {
    asm volatile("ldmatrix.sync.aligned.m8n8.x4.shared.b16 {%0,%1,%2,%3}, [%4];"
                 : "=r"(r0), "=r"(r1), "=r"(r2), "=r"(r3) : "r"(addr));
}
__device__ __forceinline__ void ldsm_x2(uint& r0, uint& r1, uint addr) {
    asm volatile("ldmatrix.sync.aligned.m8n8.x2.shared.b16 {%0,%1}, [%2];"
                 : "=r"(r0), "=r"(r1) : "r"(addr));
}
__device__ __forceinline__ void mma_bf16(float* d, const uint* a, uint b0, uint b1) {
    asm volatile(
        "mma.sync.aligned.m16n8k16.row.col.f32.bf16.bf16.f32 "
        "{%0,%1,%2,%3}, {%4,%5,%6,%7}, {%8,%9}, {%0,%1,%2,%3};"
        : "+f"(d[0]), "+f"(d[1]), "+f"(d[2]), "+f"(d[3])
        : "r"(a[0]), "r"(a[1]), "r"(a[2]), "r"(a[3]), "r"(b0), "r"(b1));
}

// ---------------- conv3x3 via bf16x3-split tensor cores ----------------
// Tile: 16x16 output px (halo 18x18), 64 oc per block. 256 threads = 8 warps,
// warp owns 32 px (2 m16-frags) x 64 oc (8 n8-frags). Cin chunks of 16.
// smem A: [pix(324)][c(16)] bf16 hi/lo, 16B slot h swizzled: h ^= (pix>>2)&1
// smem B: [tap*64+oc][c(16)] bf16 hi/lo, slot h ^= (oc>>2)&1
#define SM_AHI 0
#define SM_ALO 10368
#define SM_WHI 20736
#define SM_WLO 39168
#define SM_TOT 57600

template<bool LRELU>
__global__ __launch_bounds__(256, 2)
void conv_mma_kernel(const float* __restrict__ in,
                     const __nv_bfloat16* __restrict__ whi,
                     const __nv_bfloat16* __restrict__ wlo,
                     const float* __restrict__ bias,
                     float* __restrict__ out,
                     int Cin, int Cout, int OCPAD) {
    extern __shared__ __align__(16) unsigned char smem[];
    const uint smbase = (uint)__cvta_generic_to_shared(smem);

    const int tid = threadIdx.x;
    const int lane = tid & 31, warp = tid >> 5;
    const int ts = blockIdx.x;
    const int ty0 = (ts >> 4) * 16, tx0 = (ts & 15) * 16;
    const int ocb64 = blockIdx.y * 64;

    float d[2][8][4];
#pragma unroll
    for (int mf = 0; mf < 2; mf++)
#pragma unroll
        for (int nf = 0; nf < 8; nf++)
#pragma unroll
            for (int j = 0; j < 4; j++) d[mf][nf][j] = 0.f;

    // A ldmatrix lane mapping
    const int matA = lane >> 3;
    const int r8 = (lane & 7) | ((matA & 1) << 3);
    const int khalfA = matA >> 1;
    // B ldmatrix lane mapping
    const int matB = (lane >> 3) & 1;
    const int oclane = lane & 7;

    for (int c0 = 0; c0 < Cin; c0 += 16) {
        __syncthreads();
        // ---- fill A tile: 324 px x 8 c-pairs ----
        for (int i = tid; i < 324 * 8; i += 256) {
            int c2 = i / 324;          // c-pair 0..7
            int pix = i % 324;
            int py = pix / 18, px = pix % 18;
            int gy = ty0 + py - 1, gx = tx0 + px - 1;
            float a = 0.f, b = 0.f;
            if (gy >= 0 && gy < HH && gx >= 0 && gx < WW) {
                const float* base = in + gy * WW + gx;
                a = base[(c0 + 2 * c2) * HW];
                b = base[(c0 + 2 * c2 + 1) * HW];
            }
            __nv_bfloat16 ha = __float2bfloat16(a);
            __nv_bfloat16 hb = __float2bfloat16(b);
            __nv_bfloat16 la = __float2bfloat16(a - __bfloat162float(ha));
            __nv_bfloat16 lb = __float2bfloat16(b - __bfloat162float(hb));
            int h = c2 >> 2;
            int off = pix * 32 + ((h ^ ((pix >> 2) & 1)) << 4) + (c2 & 3) * 4;
            uint phi = ((uint)__bfloat16_as_ushort(hb) << 16) | __bfloat16_as_ushort(ha);
            uint plo = ((uint)__bfloat16_as_ushort(lb) << 16) | __bfloat16_as_ushort(la);
            *(uint*)(smem + SM_AHI + off) = phi;
            *(uint*)(smem + SM_ALO + off) = plo;
        }
        // ---- fill W tile: 9 taps x 64 oc x 16 c (16B chunks) ----
        for (int idx = tid; idx < 9 * 64 * 2; idx += 256) {
            int tap = idx / 128;
            int r = idx % 128;
            int oc = r >> 1, h = r & 1;
            long src = (long)(tap * OCPAD + ocb64 + oc) * Cin + c0 + h * 8;
            int dst = (tap * 64 + oc) * 32 + ((h ^ ((oc >> 2) & 1)) << 4);
            *(uint4*)(smem + SM_WHI + dst) = *(const uint4*)(whi + src);
            *(uint4*)(smem + SM_WLO + dst) = *(const uint4*)(wlo + src);
        }
        __syncthreads();

#pragma unroll
        for (int tap = 0; tap < 9; tap++) {
            const int dy = tap / 3, dx = tap % 3;
            uint ah[2][4], al[2][4];
#pragma unroll
            for (int mf = 0; mf < 2; mf++) {
                int m = warp * 32 + mf * 16 + r8;
                int pix = ((m >> 4) + dy) * 18 + (m & 15) + dx;
                uint off = pix * 32 + ((khalfA ^ ((pix >> 2) & 1)) << 4);
                ldsm_x4(ah[mf][0], ah[mf][1], ah[mf][2], ah[mf][3], smbase + SM_AHI + off);
                ldsm_x4(al[mf][0], al[mf][1], al[mf][2], al[mf][3], smbase + SM_ALO + off);
            }
#pragma unroll
            for (int nf = 0; nf < 8; nf++) {
                int oc8 = nf * 8 + oclane;
                uint boff = (uint)(tap * 64 + oc8) * 32 + ((matB ^ ((oc8 >> 2) & 1)) << 4);
                uint bh0, bh1, bl0, bl1;
                ldsm_x2(bh0, bh1, smbase + SM_WHI + boff);
                ldsm_x2(bl0, bl1, smbase + SM_WLO + boff);
#pragma unroll
                for (int mf = 0; mf < 2; mf++) {
                    mma_bf16(d[mf][nf], ah[mf], bh0, bh1);
                    mma_bf16(d[mf][nf], ah[mf], bl0, bl1);
                    mma_bf16(d[mf][nf], al[mf], bh0, bh1);
                }
            }
        }
    }

    // ---- store ----
    const int groupID = lane >> 2, tig = lane & 3;
#pragma unroll
    for (int mf = 0; mf < 2; mf++) {
#pragma unroll
        for (int nf = 0; nf < 8; nf++) {
#pragma unroll
            for (int j = 0; j < 4; j++) {
                int row = groupID + (j >> 1) * 8;
                int col = 2 * tig + (j & 1);
                int m = warp * 32 + mf * 16 + row;
                int gy = ty0 + (m >> 4);
                int gx = tx0 + (m & 15);
                int oc = ocb64 + nf * 8 + col;
                if (oc < Cout) {
                    float v = d[mf][nf][j] + bias[oc];
                    if (LRELU) v = v >= 0.f ? v : 0.1f * v;
                    out[oc * HW + gy * WW + gx] = v;
                }
            }
        }
    }
}

// ---------------- fused deformable gather + grouped GEMM (unchanged) ----------------
__global__ __launch_bounds__(256, 2)
void dcn_fused_kernel(const float* __restrict__ feat,
                      const float* __restrict__ offraw,
                      const float* __restrict__ flow,
                      const float* __restrict__ w,
                      const float* __restrict__ bias,
                      float* __restrict__ out) {
    __shared__ __align__(8) float s_w[72][64];

    const int tid = threadIdx.x;
    const int px = blockIdx.x * 256 + tid;
    const int y = px >> 8, x = px & 255;

    const float fly = flow[HW + px], flx = flow[px];

    ull acc[32];
#pragma unroll
    for (int p = 0; p < 32; p++) acc[p] = 0ULL;

    for (int g = 0; g < 8; g++) {
        __syncthreads();
        for (int i = tid; i < 72 * 64; i += 256) {
            int oc = i & 63, ck = i >> 6;
            s_w[ck][oc] = w[oc * 576 + g * 72 + ck];
        }
        __syncthreads();

        const float* fg = feat + g * 8 * HW;

#pragma unroll
        for (int k = 0; k < 9; k++) {
            const int gk = g * 9 + k;
            float oy = 10.f * tanhf(offraw[(gk * 2 + 0) * HW + px]) + fly;
            float ox = 10.f * tanhf(offraw[(gk * 2 + 1) * HW + px]) + flx;
            float m = 1.f / (1.f + expf(-offraw[(144 + gk) * HW + px]));

            float py = (float)y + (float)(k / 3 - 1) + oy;
            float pxx = (float)x + (float)(k % 3 - 1) + ox;
            float y0f = floorf(py), x0f = floorf(pxx);
            float ly = py - y0f, lx = pxx - x0f;
            int yi0 = (int)y0f, xi0 = (int)x0f;
            int yi1 = yi0 + 1, xi1 = xi0 + 1;
            float vy0 = (yi0 >= 0 && yi0 < HH) ? 1.f : 0.f;
            float vy1 = (yi1 >= 0 && yi1 < HH) ? 1.f : 0.f;
            float vx0 = (xi0 >= 0 && xi0 < WW) ? 1.f : 0.f;
            float vx1 = (xi1 >= 0 && xi1 < WW) ? 1.f : 0.f;
            int yc0 = min(max(yi0, 0), HH - 1), yc1 = min(max(yi1, 0), HH - 1);
            int xc0 = min(max(xi0, 0), WW - 1), xc1 = min(max(xi1, 0), WW - 1);
            float w00 = (1.f - ly) * (1.f - lx) * vy0 * vx0 * m;
            float w01 = (1.f - ly) * lx * vy0 * vx1 * m;
            float w10 = ly * (1.f - lx) * vy1 * vx0 * m;
            float w11 = ly * lx * vy1 * vx1 * m;
            int i00 = yc0 * WW + xc0, i01 = yc0 * WW + xc1;
            int i10 = yc1 * WW + xc0, i11 = yc1 * WW + xc1;

#pragma unroll
            for (int c = 0; c < 8; c++) {
                const float* fc = fg + c * HW;
                float v = w00 * fc[i00] + w01 * fc[i01] + w10 * fc[i10] + w11 * fc[i11];
                ull sv;
                asm("mov.b64 %0, {%1, %1};" : "=l"(sv) : "f"(v));
                const int row = c * 9 + k;
#pragma unroll
                for (int p = 0; p < 32; p++) {
                    ull wp = *reinterpret_cast<const ull*>(&s_w[row][2 * p]);
                    asm("fma.rn.f32x2 %0, %1, %2, %0;" : "+l"(acc[p]) : "l"(sv), "l"(wp));
                }
            }
        }
    }

#pragma unroll
    for (int p = 0; p < 32; p++) {
        int oc0 = 2 * p, oc1 = oc0 + 1;
        float a0, a1;
        asm("mov.b64 {%0, %1}, %2;" : "=f"(a0), "=f"(a1) : "l"(acc[p]));
        out[oc0 * HW + px] = a0 + bias[oc0];
        out[oc1 * HW + px] = a1 + bias[oc1];
    }
}

// ---------------- host side ----------------
#define L0_OFF 0
#define L1_OFF 73728
#define L2_OFF 110592
#define L3_OFF 147456
#define BR_SZ  294912
#define FUS_OFF 589824

static void conv_mma(const float* in, const __nv_bfloat16* whi, const __nv_bfloat16* wlo,
                     const float* bias, float* out, int Cin, int Cout, int OCPAD, bool lrelu) {
    dim3 grid(256, OCPAD / 64);
    if (lrelu)
        conv_mma_kernel<true><<<grid, 256, SM_TOT>>>(in, whi, wlo, bias, out, Cin, Cout, OCPAD);
    else
        conv_mma_kernel<false><<<grid, 256, SM_TOT>>>(in, whi, wlo, bias, out, Cin, Cout, OCPAD);
}

static void prep_weights(const float* w, __nv_bfloat16* hi, __nv_bfloat16* lo,
                         int Cout, int Cin, int OCPAD) {
    int total = 9 * OCPAD * Cin;
    wconv_kernel<<<(total + 255) / 256, 256>>>(w, hi, lo, Cout, Cin, OCPAD);
}

static void run_branch(const float* feat, const float* extra, const float* flow,
                       const float* b0, const float* b1, const float* b2, const float* b3,
                       const __nv_bfloat16* whi, const __nv_bfloat16* wlo,
                       const float* dw, const float* db,
                       float* t1, float* t2, float* off, float* branch_out) {
    conv_mma(extra, whi + L0_OFF, wlo + L0_OFF, b0, t1, 128, 64, 64, true);
    conv_mma(t1,    whi + L1_OFF, wlo + L1_OFF, b1, t2,  64, 64, 64, true);
    conv_mma(t2,    whi + L2_OFF, wlo + L2_OFF, b2, t1,  64, 64, 64, true);
    conv_mma(t1,    whi + L3_OFF, wlo + L3_OFF, b3, off, 64, 216, 256, false);
    dcn_fused_kernel<<<HW / 256, 256>>>(feat, off, flow, dw, db, branch_out);
}

extern "C" void kernel_launch(void* const* d_in, const int* in_sizes, int n_in,
                              void* d_out, int out_size) {
    const float* feat_prev  = (const float*)d_in[0];
    const float* feat_next  = (const float*)d_in[1];
    const float* extra_prev = (const float*)d_in[2];
    const float* extra_next = (const float*)d_in[3];
    const float* flow_prev  = (const float*)d_in[4];
    const float* flow_next  = (const float*)d_in[5];
    const float* dcn1_w = (const float*)d_in[22];
    const float* dcn1_b = (const float*)d_in[23];
    const float* dcn2_w = (const float*)d_in[24];
    const float* dcn2_b = (const float*)d_in[25];
    const float* fus_w  = (const float*)d_in[26];
    const float* fus_b  = (const float*)d_in[27];

    float *t1, *t2, *off, *cat;
    __nv_bfloat16 *whi, *wlo;
    cudaGetSymbolAddress((void**)&t1,  g_t1);
    cudaGetSymbolAddress((void**)&t2,  g_t2);
    cudaGetSymbolAddress((void**)&off, g_off);
    cudaGetSymbolAddress((void**)&cat, g_cat);
    cudaGetSymbolAddress((void**)&whi, g_whi);
    cudaGetSymbolAddress((void**)&wlo, g_wlo);

    cudaFuncSetAttribute(conv_mma_kernel<true>,
                         cudaFuncAttributeMaxDynamicSharedMemorySize, SM_TOT);
    cudaFuncSetAttribute(conv_mma_kernel<false>,
                         cudaFuncAttributeMaxDynamicSharedMemorySize, SM_TOT);

    // pre-convert all conv weights to bf16 hi/lo
    prep_weights((const float*)d_in[6],  whi + L0_OFF,          wlo + L0_OFF,          64, 128, 64);
    prep_weights((const float*)d_in[8],  whi + L1_OFF,          wlo + L1_OFF,          64,  64, 64);
    prep_weights((const float*)d_in[10], whi + L2_OFF,          wlo + L2_OFF,          64,  64, 64);
    prep_weights((const float*)d_in[12], whi + L3_OFF,          wlo + L3_OFF,         216,  64, 256);
    prep_weights((const float*)d_in[14], whi + BR_SZ + L0_OFF,  wlo + BR_SZ + L0_OFF,  64, 128, 64);
    prep_weights((const float*)d_in[16], whi + BR_SZ + L1_OFF,  wlo + BR_SZ + L1_OFF,  64,  64, 64);
    prep_weights((const float*)d_in[18], whi + BR_SZ + L2_OFF,  wlo + BR_SZ + L2_OFF,  64,  64, 64);
    prep_weights((const float*)d_in[20], whi + BR_SZ + L3_OFF,  wlo + BR_SZ + L3_OFF, 216,  64, 256);
    prep_weights(fus_w,                  whi + FUS_OFF,         wlo + FUS_OFF,         64, 128, 64);

    run_branch(feat_prev, extra_prev, flow_prev,
               (const float*)d_in[7], (const float*)d_in[9],
               (const float*)d_in[11], (const float*)d_in[13],
               whi, wlo, dcn1_w, dcn1_b, t1, t2, off, cat);

    run_branch(feat_next, extra_next, flow_next,
               (const float*)d_in[15], (const float*)d_in[17],
               (const float*)d_in[19], (const float*)d_in[21],
               whi + BR_SZ, wlo + BR_SZ, dcn2_w, dcn2_b, t1, t2, off, cat + 64 * HW);

    conv_mma(cat, whi + FUS_OFF, wlo + FUS_OFF, fus_b, (float*)d_out, 128, 64, 64, false);
}

// round 7
// speedup vs baseline: 2.2089x; 1.5709x over previous
#include <cuda_runtime.h>
#include <cuda_bf16.h>
#include <math.h>

#define HH 256
#define WW 256
#define HW (HH*WW)

typedef unsigned int uint;
typedef unsigned long long ull;

// ---------------- scratch (static device globals; no allocs) ----------------
__device__ float g_t1[64 * HW];
__device__ float g_t2[64 * HW];
__device__ float g_off[216 * HW];
__device__ float g_cat[128 * HW];
__device__ __align__(16) float g_featT[2 * 64 * HW];   // NHWC transposed feats

// pre-converted bf16 hi/lo weights, layout [tap][OCPAD][Cin] per layer
#define L0_OFF 0
#define L1_OFF 73728
#define L2_OFF 110592
#define L3_OFF 147456
#define BR_SZ  294912
#define FUS_OFF 589824
#define W_TOTAL 663552
__device__ __align__(16) __nv_bfloat16 g_whi[W_TOTAL];
__device__ __align__(16) __nv_bfloat16 g_wlo[W_TOTAL];

// ---------------- batched weight pre-convert (all 9 layers, one launch) ----------------
__global__ void wconv_all_kernel(const float* w0, const float* w1, const float* w2, const float* w3,
                                 const float* w4, const float* w5, const float* w6, const float* w7,
                                 const float* w8,
                                 __nv_bfloat16* __restrict__ dhi,
                                 __nv_bfloat16* __restrict__ dlo) {
    int i = blockIdx.x * 256 + threadIdx.x;
    if (i >= W_TOTAL) return;
    // segment table: {offset, Cout, Cin, OCPAD}
    const float* w;
    int base, Cout, Cin, OCPAD;
    if      (i < L1_OFF)          { w = w0; base = L0_OFF;          Cout = 64;  Cin = 128; OCPAD = 64;  }
    else if (i < L2_OFF)          { w = w1; base = L1_OFF;          Cout = 64;  Cin = 64;  OCPAD = 64;  }
    else if (i < L3_OFF)          { w = w2; base = L2_OFF;          Cout = 64;  Cin = 64;  OCPAD = 64;  }
    else if (i < BR_SZ)           { w = w3; base = L3_OFF;          Cout = 216; Cin = 64;  OCPAD = 256; }
    else if (i < BR_SZ + L1_OFF)  { w = w4; base = BR_SZ + L0_OFF;  Cout = 64;  Cin = 128; OCPAD = 64;  }
    else if (i < BR_SZ + L2_OFF)  { w = w5; base = BR_SZ + L1_OFF;  Cout = 64;  Cin = 64;  OCPAD = 64;  }
    else if (i < BR_SZ + L3_OFF)  { w = w6; base = BR_SZ + L2_OFF;  Cout = 64;  Cin = 64;  OCPAD = 64;  }
    else if (i < FUS_OFF)         { w = w7; base = BR_SZ + L3_OFF;  Cout = 216; Cin = 64;  OCPAD = 256; }
    else                          { w = w8; base = FUS_OFF;         Cout = 64;  Cin = 128; OCPAD = 64;  }
    int li = i - base;
    int c = li % Cin;
    int rem = li / Cin;
    int oc = rem % OCPAD;
    int tap = rem / OCPAD;
    float v = 0.f;
    if (oc < Cout) v = w[(oc * Cin + c) * 9 + tap];
    __nv_bfloat16 hi = __float2bfloat16(v);
    float r = v - __bfloat162float(hi);
    dhi[i] = hi;
    dlo[i] = __float2bfloat16(r);
}

// ---------------- CHW -> HWC transpose (64 channels) ----------------
// Block: 256 threads handles 64 px x 64 c through smem.
__global__ void transpose_kernel(const float* __restrict__ in, float* __restrict__ out) {
    __shared__ float s[64][65];
    const int tid = threadIdx.x;
    const int px0 = blockIdx.x * 64;
    // read: coalesced over px
    for (int j = 0; j < 16; j++) {
        int idx = j * 256 + tid;
        int c = idx >> 6, p = idx & 63;
        s[p][c] = in[c * HW + px0 + p];
    }
    __syncthreads();
    // write: coalesced over c
    for (int j = 0; j < 16; j++) {
        int p = j * 4 + (tid >> 6), c = tid & 63;
        out[(px0 + p) * 64 + c] = s[p][c];
    }
}

// ---------------- mma helpers ----------------
__device__ __forceinline__ void ldsm_x4(uint& r0, uint& r1, uint& r2, uint& r3, uint addr) {
    asm volatile("ldmatrix.sync.aligned.m8n8.x4.shared.b16 {%0,%1,%2,%3}, [%4];"
                 : "=r"(r0), "=r"(r1), "=r"(r2), "=r"(r3) : "r"(addr));
}
__device__ __forceinline__ void ldsm_x2(uint& r0, uint& r1, uint addr) {
    asm volatile("ldmatrix.sync.aligned.m8n8.x2.shared.b16 {%0,%1}, [%2];"
                 : "=r"(r0), "=r"(r1) : "r"(addr));
}
__device__ __forceinline__ void mma_bf16(float* d, const uint* a, uint b0, uint b1) {
    asm volatile(
        "mma.sync.aligned.m16n8k16.row.col.f32.bf16.bf16.f32 "
        "{%0,%1,%2,%3}, {%4,%5,%6,%7}, {%8,%9}, {%0,%1,%2,%3};"
        : "+f"(d[0]), "+f"(d[1]), "+f"(d[2]), "+f"(d[3])
        : "r"(a[0]), "r"(a[1]), "r"(a[2]), "r"(a[3]), "r"(b0), "r"(b1));
}

// fast transcendentals (MUFU-based; rel err ~3e-6)
__device__ __forceinline__ float ftanh(float x) {
    float e = __expf(2.f * x);
    return 1.f - __fdividef(2.f, e + 1.f);
}
__device__ __forceinline__ float fsigmoid(float x) {
    return __fdividef(1.f, 1.f + __expf(-x));
}

// ---------------- conv3x3 via bf16x3-split tensor cores (as R5) ----------------
#define SM_AHI 0
#define SM_ALO 10368
#define SM_WHI 20736
#define SM_WLO 39168
#define SM_TOT 57600

template<bool LRELU>
__global__ __launch_bounds__(256, 2)
void conv_mma_kernel(const float* __restrict__ in,
                     const __nv_bfloat16* __restrict__ whi,
                     const __nv_bfloat16* __restrict__ wlo,
                     const float* __restrict__ bias,
                     float* __restrict__ out,
                     int Cin, int Cout, int OCPAD) {
    extern __shared__ __align__(16) unsigned char smem[];
    const uint smbase = (uint)__cvta_generic_to_shared(smem);

    const int tid = threadIdx.x;
    const int lane = tid & 31, warp = tid >> 5;
    const int ts = blockIdx.x;
    const int ty0 = (ts >> 4) * 16, tx0 = (ts & 15) * 16;
    const int ocb64 = blockIdx.y * 64;

    float d[2][8][4];
#pragma unroll
    for (int mf = 0; mf < 2; mf++)
#pragma unroll
        for (int nf = 0; nf < 8; nf++)
#pragma unroll
            for (int j = 0; j < 4; j++) d[mf][nf][j] = 0.f;

    const int matA = lane >> 3;
    const int r8 = (lane & 7) | ((matA & 1) << 3);
    const int khalfA = matA >> 1;
    const int matB = (lane >> 3) & 1;
    const int oclane = lane & 7;

    for (int c0 = 0; c0 < Cin; c0 += 16) {
        __syncthreads();
        for (int i = tid; i < 324 * 8; i += 256) {
            int c2 = i / 324;
            int pix = i % 324;
            int py = pix / 18, px = pix % 18;
            int gy = ty0 + py - 1, gx = tx0 + px - 1;
            float a = 0.f, b = 0.f;
            if (gy >= 0 && gy < HH && gx >= 0 && gx < WW) {
                const float* base = in + gy * WW + gx;
                a = base[(c0 + 2 * c2) * HW];
                b = base[(c0 + 2 * c2 + 1) * HW];
            }
            __nv_bfloat16 ha = __float2bfloat16(a);
            __nv_bfloat16 hb = __float2bfloat16(b);
            __nv_bfloat16 la = __float2bfloat16(a - __bfloat162float(ha));
            __nv_bfloat16 lb = __float2bfloat16(b - __bfloat162float(hb));
            int h = c2 >> 2;
            int off = pix * 32 + ((h ^ ((pix >> 2) & 1)) << 4) + (c2 & 3) * 4;
            uint phi = ((uint)__bfloat16_as_ushort(hb) << 16) | __bfloat16_as_ushort(ha);
            uint plo = ((uint)__bfloat16_as_ushort(lb) << 16) | __bfloat16_as_ushort(la);
            *(uint*)(smem + SM_AHI + off) = phi;
            *(uint*)(smem + SM_ALO + off) = plo;
        }
        for (int idx = tid; idx < 9 * 64 * 2; idx += 256) {
            int tap = idx / 128;
            int r = idx % 128;
            int oc = r >> 1, h = r & 1;
            long src = (long)(tap * OCPAD + ocb64 + oc) * Cin + c0 + h * 8;
            int dst = (tap * 64 + oc) * 32 + ((h ^ ((oc >> 2) & 1)) << 4);
            *(uint4*)(smem + SM_WHI + dst) = *(const uint4*)(whi + src);
            *(uint4*)(smem + SM_WLO + dst) = *(const uint4*)(wlo + src);
        }
        __syncthreads();

#pragma unroll
        for (int tap = 0; tap < 9; tap++) {
            const int dy = tap / 3, dx = tap % 3;
            uint ah[2][4], al[2][4];
#pragma unroll
            for (int mf = 0; mf < 2; mf++) {
                int m = warp * 32 + mf * 16 + r8;
                int pix = ((m >> 4) + dy) * 18 + (m & 15) + dx;
                uint off = pix * 32 + ((khalfA ^ ((pix >> 2) & 1)) << 4);
                ldsm_x4(ah[mf][0], ah[mf][1], ah[mf][2], ah[mf][3], smbase + SM_AHI + off);
                ldsm_x4(al[mf][0], al[mf][1], al[mf][2], al[mf][3], smbase + SM_ALO + off);
            }
#pragma unroll
            for (int nf = 0; nf < 8; nf++) {
                int oc8 = nf * 8 + oclane;
                uint boff = (uint)(tap * 64 + oc8) * 32 + ((matB ^ ((oc8 >> 2) & 1)) << 4);
                uint bh0, bh1, bl0, bl1;
                ldsm_x2(bh0, bh1, smbase + SM_WHI + boff);
                ldsm_x2(bl0, bl1, smbase + SM_WLO + boff);
#pragma unroll
                for (int mf = 0; mf < 2; mf++) {
                    mma_bf16(d[mf][nf], ah[mf], bh0, bh1);
                    mma_bf16(d[mf][nf], ah[mf], bl0, bl1);
                    mma_bf16(d[mf][nf], al[mf], bh0, bh1);
                }
            }
        }
    }

    const int groupID = lane >> 2, tig = lane & 3;
#pragma unroll
    for (int mf = 0; mf < 2; mf++) {
#pragma unroll
        for (int nf = 0; nf < 8; nf++) {
#pragma unroll
            for (int j = 0; j < 4; j++) {
                int row = groupID + (j >> 1) * 8;
                int col = 2 * tig + (j & 1);
                int m = warp * 32 + mf * 16 + row;
                int gy = ty0 + (m >> 4);
                int gx = tx0 + (m & 15);
                int oc = ocb64 + nf * 8 + col;
                if (oc < Cout) {
                    float v = d[mf][nf][j] + bias[oc];
                    if (LRELU) v = v >= 0.f ? v : 0.1f * v;
                    out[oc * HW + gy * WW + gx] = v;
                }
            }
        }
    }
}

// ---------------- fused deformable gather + grouped GEMM (NHWC feat) ----------------
__global__ __launch_bounds__(256, 2)
void dcn_fused_kernel(const float* __restrict__ featT,     // [HW][64]
                      const float* __restrict__ offraw,
                      const float* __restrict__ flow,
                      const float* __restrict__ w,
                      const float* __restrict__ bias,
                      float* __restrict__ out) {
    __shared__ __align__(8) float s_w[72][64];

    const int tid = threadIdx.x;
    const int px = blockIdx.x * 256 + tid;
    const int y = px >> 8, x = px & 255;

    const float fly = flow[HW + px], flx = flow[px];

    ull acc[32];
#pragma unroll
    for (int p = 0; p < 32; p++) acc[p] = 0ULL;

    for (int g = 0; g < 8; g++) {
        __syncthreads();
        for (int i = tid; i < 72 * 64; i += 256) {
            int oc = i & 63, ck = i >> 6;
            s_w[ck][oc] = w[oc * 576 + g * 72 + ck];
        }
        __syncthreads();

#pragma unroll
        for (int k = 0; k < 9; k++) {
            const int gk = g * 9 + k;
            float oy = 10.f * ftanh(offraw[(gk * 2 + 0) * HW + px]) + fly;
            float ox = 10.f * ftanh(offraw[(gk * 2 + 1) * HW + px]) + flx;
            float m = fsigmoid(offraw[(144 + gk) * HW + px]);

            float py = (float)y + (float)(k / 3 - 1) + oy;
            float pxx = (float)x + (float)(k % 3 - 1) + ox;
            float y0f = floorf(py), x0f = floorf(pxx);
            float ly = py - y0f, lx = pxx - x0f;
            int yi0 = (int)y0f, xi0 = (int)x0f;
            int yi1 = yi0 + 1, xi1 = xi0 + 1;
            float vy0 = (yi0 >= 0 && yi0 < HH) ? 1.f : 0.f;
            float vy1 = (yi1 >= 0 && yi1 < HH) ? 1.f : 0.f;
            float vx0 = (xi0 >= 0 && xi0 < WW) ? 1.f : 0.f;
            float vx1 = (xi1 >= 0 && xi1 < WW) ? 1.f : 0.f;
            int yc0 = min(max(yi0, 0), HH - 1), yc1 = min(max(yi1, 0), HH - 1);
            int xc0 = min(max(xi0, 0), WW - 1), xc1 = min(max(xi1, 0), WW - 1);
            float w00 = (1.f - ly) * (1.f - lx) * vy0 * vx0 * m;
            float w01 = (1.f - ly) * lx * vy0 * vx1 * m;
            float w10 = ly * (1.f - lx) * vy1 * vx0 * m;
            float w11 = ly * lx * vy1 * vx1 * m;

            const float* p00 = featT + (yc0 * WW + xc0) * 64 + g * 8;
            const float* p01 = featT + (yc0 * WW + xc1) * 64 + g * 8;
            const float* p10 = featT + (yc1 * WW + xc0) * 64 + g * 8;
            const float* p11 = featT + (yc1 * WW + xc1) * 64 + g * 8;

            float v[8];
#pragma unroll
            for (int h = 0; h < 2; h++) {
                float4 a00 = *(const float4*)(p00 + 4 * h);
                float4 a01 = *(const float4*)(p01 + 4 * h);
                float4 a10 = *(const float4*)(p10 + 4 * h);
                float4 a11 = *(const float4*)(p11 + 4 * h);
                v[4 * h + 0] = w00 * a00.x + w01 * a01.x + w10 * a10.x + w11 * a11.x;
                v[4 * h + 1] = w00 * a00.y + w01 * a01.y + w10 * a10.y + w11 * a11.y;
                v[4 * h + 2] = w00 * a00.z + w01 * a01.z + w10 * a10.z + w11 * a11.z;
                v[4 * h + 3] = w00 * a00.w + w01 * a01.w + w10 * a10.w + w11 * a11.w;
            }

#pragma unroll
            for (int c = 0; c < 8; c++) {
                ull sv;
                asm("mov.b64 %0, {%1, %1};" : "=l"(sv) : "f"(v[c]));
                const int row = c * 9 + k;
#pragma unroll
                for (int p = 0; p < 32; p++) {
                    ull wp = *reinterpret_cast<const ull*>(&s_w[row][2 * p]);
                    asm("fma.rn.f32x2 %0, %1, %2, %0;" : "+l"(acc[p]) : "l"(sv), "l"(wp));
                }
            }
        }
    }

#pragma unroll
    for (int p = 0; p < 32; p++) {
        int oc0 = 2 * p, oc1 = oc0 + 1;
        float a0, a1;
        asm("mov.b64 {%0, %1}, %2;" : "=f"(a0), "=f"(a1) : "l"(acc[p]));
        out[oc0 * HW + px] = a0 + bias[oc0];
        out[oc1 * HW + px] = a1 + bias[oc1];
    }
}

// ---------------- host side ----------------
static void conv_mma(const float* in, const __nv_bfloat16* whi, const __nv_bfloat16* wlo,
                     const float* bias, float* out, int Cin, int Cout, int OCPAD, bool lrelu) {
    dim3 grid(256, OCPAD / 64);
    if (lrelu)
        conv_mma_kernel<true><<<grid, 256, SM_TOT>>>(in, whi, wlo, bias, out, Cin, Cout, OCPAD);
    else
        conv_mma_kernel<false><<<grid, 256, SM_TOT>>>(in, whi, wlo, bias, out, Cin, Cout, OCPAD);
}

static void run_branch(const float* featT, const float* extra, const float* flow,
                       const float* b0, const float* b1, const float* b2, const float* b3,
                       const __nv_bfloat16* whi, const __nv_bfloat16* wlo,
                       const float* dw, const float* db,
                       float* t1, float* t2, float* off, float* branch_out) {
    conv_mma(extra, whi + L0_OFF, wlo + L0_OFF, b0, t1, 128, 64, 64, true);
    conv_mma(t1,    whi + L1_OFF, wlo + L1_OFF, b1, t2,  64, 64, 64, true);
    conv_mma(t2,    whi + L2_OFF, wlo + L2_OFF, b2, t1,  64, 64, 64, true);
    conv_mma(t1,    whi + L3_OFF, wlo + L3_OFF, b3, off, 64, 216, 256, false);
    dcn_fused_kernel<<<HW / 256, 256>>>(featT, off, flow, dw, db, branch_out);
}

extern "C" void kernel_launch(void* const* d_in, const int* in_sizes, int n_in,
                              void* d_out, int out_size) {
    const float* feat_prev  = (const float*)d_in[0];
    const float* feat_next  = (const float*)d_in[1];
    const float* extra_prev = (const float*)d_in[2];
    const float* extra_next = (const float*)d_in[3];
    const float* flow_prev  = (const float*)d_in[4];
    const float* flow_next  = (const float*)d_in[5];
    const float* dcn1_w = (const float*)d_in[22];
    const float* dcn1_b = (const float*)d_in[23];
    const float* dcn2_w = (const float*)d_in[24];
    const float* dcn2_b = (const float*)d_in[25];
    const float* fus_w  = (const float*)d_in[26];
    const float* fus_b  = (const float*)d_in[27];

    float *t1, *t2, *off, *cat, *featT;
    __nv_bfloat16 *whi, *wlo;
    cudaGetSymbolAddress((void**)&t1,  g_t1);
    cudaGetSymbolAddress((void**)&t2,  g_t2);
    cudaGetSymbolAddress((void**)&off, g_off);
    cudaGetSymbolAddress((void**)&cat, g_cat);
    cudaGetSymbolAddress((void**)&featT, g_featT);
    cudaGetSymbolAddress((void**)&whi, g_whi);
    cudaGetSymbolAddress((void**)&wlo, g_wlo);

    cudaFuncSetAttribute(conv_mma_kernel<true>,
                         cudaFuncAttributeMaxDynamicSharedMemorySize, SM_TOT);
    cudaFuncSetAttribute(conv_mma_kernel<false>,
                         cudaFuncAttributeMaxDynamicSharedMemorySize, SM_TOT);

    // one-shot weight conversion (all 9 conv layers)
    wconv_all_kernel<<<(W_TOTAL + 255) / 256, 256>>>(
        (const float*)d_in[6],  (const float*)d_in[8],  (const float*)d_in[10], (const float*)d_in[12],
        (const float*)d_in[14], (const float*)d_in[16], (const float*)d_in[18], (const float*)d_in[20],
        fus_w, whi, wlo);

    // feat CHW -> HWC
    transpose_kernel<<<HW / 64, 256>>>(feat_prev, featT);
    transpose_kernel<<<HW / 64, 256>>>(feat_next, featT + 64 * HW);

    run_branch(featT, extra_prev, flow_prev,
               (const float*)d_in[7], (const float*)d_in[9],
               (const float*)d_in[11], (const float*)d_in[13],
               whi, wlo, dcn1_w, dcn1_b, t1, t2, off, cat);

    run_branch(featT + 64 * HW, extra_next, flow_next,
               (const float*)d_in[15], (const float*)d_in[17],
               (const float*)d_in[19], (const float*)d_in[21],
               whi + BR_SZ, wlo + BR_SZ, dcn2_w, dcn2_b, t1, t2, off, cat + 64 * HW);

    conv_mma(cat, whi + FUS_OFF, wlo + FUS_OFF, fus_b, (float*)d_out, 128, 64, 64, false);
}

// round 8
// speedup vs baseline: 2.2705x; 1.0279x over previous
#include <cuda_runtime.h>
#include <cuda_bf16.h>
#include <math.h>

#define HH 256
#define WW 256
#define HW (HH*WW)

typedef unsigned int uint;
typedef unsigned long long ull;

// ---------------- scratch (static device globals; no allocs) ----------------
__device__ float g_off[216 * HW];
__device__ float g_cat[128 * HW];
__device__ __align__(16) float g_featT[2 * 64 * HW];   // NHWC fp32 feats for gather

// split-bf16 NHWC activations
__device__ __align__(16) __nv_bfloat16 g_ext_hi[128 * HW];
__device__ __align__(16) __nv_bfloat16 g_ext_lo[128 * HW];
__device__ __align__(16) __nv_bfloat16 g_a_hi[64 * HW];
__device__ __align__(16) __nv_bfloat16 g_a_lo[64 * HW];
__device__ __align__(16) __nv_bfloat16 g_b_hi[64 * HW];
__device__ __align__(16) __nv_bfloat16 g_b_lo[64 * HW];

// pre-converted bf16 hi/lo weights, layout [tap][OCPAD][Cin] per layer
#define L0_OFF 0
#define L1_OFF 73728
#define L2_OFF 110592
#define L3_OFF 147456
#define BR_SZ  294912
#define FUS_OFF 589824
#define W_TOTAL 663552
__device__ __align__(16) __nv_bfloat16 g_whi[W_TOTAL];
__device__ __align__(16) __nv_bfloat16 g_wlo[W_TOTAL];

// ---------------- batched weight pre-convert (all 9 layers, one launch) ----------------
__global__ void wconv_all_kernel(const float* w0, const float* w1, const float* w2, const float* w3,
                                 const float* w4, const float* w5, const float* w6, const float* w7,
                                 const float* w8,
                                 __nv_bfloat16* __restrict__ dhi,
                                 __nv_bfloat16* __restrict__ dlo) {
    int i = blockIdx.x * 256 + threadIdx.x;
    if (i >= W_TOTAL) return;
    const float* w;
    int base, Cout, Cin, OCPAD;
    if      (i < L1_OFF)          { w = w0; base = L0_OFF;          Cout = 64;  Cin = 128; OCPAD = 64;  }
    else if (i < L2_OFF)          { w = w1; base = L1_OFF;          Cout = 64;  Cin = 64;  OCPAD = 64;  }
    else if (i < L3_OFF)          { w = w2; base = L2_OFF;          Cout = 64;  Cin = 64;  OCPAD = 64;  }
    else if (i < BR_SZ)           { w = w3; base = L3_OFF;          Cout = 216; Cin = 64;  OCPAD = 256; }
    else if (i < BR_SZ + L1_OFF)  { w = w4; base = BR_SZ + L0_OFF;  Cout = 64;  Cin = 128; OCPAD = 64;  }
    else if (i < BR_SZ + L2_OFF)  { w = w5; base = BR_SZ + L1_OFF;  Cout = 64;  Cin = 64;  OCPAD = 64;  }
    else if (i < BR_SZ + L3_OFF)  { w = w6; base = BR_SZ + L2_OFF;  Cout = 64;  Cin = 64;  OCPAD = 64;  }
    else if (i < FUS_OFF)         { w = w7; base = BR_SZ + L3_OFF;  Cout = 216; Cin = 64;  OCPAD = 256; }
    else                          { w = w8; base = FUS_OFF;         Cout = 64;  Cin = 128; OCPAD = 64;  }
    int li = i - base;
    int c = li % Cin;
    int rem = li / Cin;
    int oc = rem % OCPAD;
    int tap = rem / OCPAD;
    float v = 0.f;
    if (oc < Cout) v = w[(oc * Cin + c) * 9 + tap];
    __nv_bfloat16 hi = __float2bfloat16(v);
    float r = v - __bfloat162float(hi);
    dhi[i] = hi;
    dlo[i] = __float2bfloat16(r);
}

// ---------------- CHW fp32 -> HWC fp32 (64 ch, for gather) ----------------
__global__ void transpose_kernel(const float* __restrict__ in, float* __restrict__ out) {
    __shared__ float s[64][65];
    const int tid = threadIdx.x;
    const int px0 = blockIdx.x * 64;
    for (int j = 0; j < 16; j++) {
        int idx = j * 256 + tid;
        int c = idx >> 6, p = idx & 63;
        s[p][c] = in[c * HW + px0 + p];
    }
    __syncthreads();
    for (int j = 0; j < 16; j++) {
        int p = j * 4 + (tid >> 6), c = tid & 63;
        out[(px0 + p) * 64 + c] = s[p][c];
    }
}

// ---------------- CHW fp32 (128ch) -> HWC split-bf16 hi/lo ----------------
__global__ void split_transpose_kernel(const float* __restrict__ in,
                                       __nv_bfloat16* __restrict__ ohi,
                                       __nv_bfloat16* __restrict__ olo) {
    __shared__ float s[128][65];
    const int tid = threadIdx.x;
    const int px0 = blockIdx.x * 64;
    {
        int cc = tid >> 6, p = tid & 63;
        for (int c = cc; c < 128; c += 4)
            s[c][p] = in[c * HW + px0 + p];
    }
    __syncthreads();
    {
        int c = tid & 127, pp0 = tid >> 7;
        for (int p = pp0; p < 64; p += 2) {
            float v = s[c][p];
            __nv_bfloat16 h = __float2bfloat16(v);
            __nv_bfloat16 l = __float2bfloat16(v - __bfloat162float(h));
            ohi[(px0 + p) * 128 + c] = h;
            olo[(px0 + p) * 128 + c] = l;
        }
    }
}

// ---------------- mma helpers ----------------
__device__ __forceinline__ void ldsm_x4(uint& r0, uint& r1, uint& r2, uint& r3, uint addr) {
    asm volatile("ldmatrix.sync.aligned.m8n8.x4.shared.b16 {%0,%1,%2,%3}, [%4];"
                 : "=r"(r0), "=r"(r1), "=r"(r2), "=r"(r3) : "r"(addr));
}
__device__ __forceinline__ void ldsm_x2(uint& r0, uint& r1, uint addr) {
    asm volatile("ldmatrix.sync.aligned.m8n8.x2.shared.b16 {%0,%1}, [%2];"
                 : "=r"(r0), "=r"(r1) : "r"(addr));
}
__device__ __forceinline__ void mma_bf16(float* d, const uint* a, uint b0, uint b1) {
    asm volatile(
        "mma.sync.aligned.m16n8k16.row.col.f32.bf16.bf16.f32 "
        "{%0,%1,%2,%3}, {%4,%5,%6,%7}, {%8,%9}, {%0,%1,%2,%3};"
        : "+f"(d[0]), "+f"(d[1]), "+f"(d[2]), "+f"(d[3])
        : "r"(a[0]), "r"(a[1]), "r"(a[2]), "r"(a[3]), "r"(b0), "r"(b1));
}

__device__ __forceinline__ float ftanh(float x) {
    float e = __expf(2.f * x);
    return 1.f - __fdividef(2.f, e + 1.f);
}
__device__ __forceinline__ float fsigmoid(float x) {
    return __fdividef(1.f, 1.f + __expf(-x));
}

// ---------------- conv3x3 via bf16x3-split tensor cores ----------------
#define SM_AHI 0
#define SM_ALO 10368
#define SM_WHI 20736
#define SM_WLO 39168
#define SM_TOT 57600

template<bool LRELU, bool BF16IN, bool BF16OUT>
__global__ __launch_bounds__(256, 2)
void conv_mma_kernel(const float* __restrict__ in_f32,
                     const __nv_bfloat16* __restrict__ in_hi,
                     const __nv_bfloat16* __restrict__ in_lo,
                     const __nv_bfloat16* __restrict__ whi,
                     const __nv_bfloat16* __restrict__ wlo,
                     const float* __restrict__ bias,
                     float* __restrict__ out_f32,
                     __nv_bfloat16* __restrict__ out_hi,
                     __nv_bfloat16* __restrict__ out_lo,
                     int Cin, int Cout, int OCPAD) {
    extern __shared__ __align__(16) unsigned char smem[];
    const uint smbase = (uint)__cvta_generic_to_shared(smem);

    const int tid = threadIdx.x;
    const int lane = tid & 31, warp = tid >> 5;
    const int ts = blockIdx.x;
    const int ty0 = (ts >> 4) * 16, tx0 = (ts & 15) * 16;
    const int ocb64 = blockIdx.y * 64;

    float d[2][8][4];
#pragma unroll
    for (int mf = 0; mf < 2; mf++)
#pragma unroll
        for (int nf = 0; nf < 8; nf++)
#pragma unroll
            for (int j = 0; j < 4; j++) d[mf][nf][j] = 0.f;

    const int matA = lane >> 3;
    const int r8 = (lane & 7) | ((matA & 1) << 3);
    const int khalfA = matA >> 1;
    const int matB = (lane >> 3) & 1;
    const int oclane = lane & 7;

    for (int c0 = 0; c0 < Cin; c0 += 16) {
        __syncthreads();
        if (BF16IN) {
            // A-fill: straight uint4 copies from pre-split NHWC bf16
            for (int i = tid; i < 324 * 2; i += 256) {
                int pix = i >> 1, h = i & 1;
                int py = pix / 18, px = pix % 18;
                int gy = ty0 + py - 1, gx = tx0 + px - 1;
                uint4 vh = make_uint4(0, 0, 0, 0), vl = make_uint4(0, 0, 0, 0);
                if (gy >= 0 && gy < HH && gx >= 0 && gx < WW) {
                    long src = (long)(gy * WW + gx) * Cin + c0 + h * 8;
                    vh = *(const uint4*)(in_hi + src);
                    vl = *(const uint4*)(in_lo + src);
                }
                int off = pix * 32 + ((h ^ ((pix >> 2) & 1)) << 4);
                *(uint4*)(smem + SM_AHI + off) = vh;
                *(uint4*)(smem + SM_ALO + off) = vl;
            }
        } else {
            for (int i = tid; i < 324 * 8; i += 256) {
                int c2 = i / 324;
                int pix = i % 324;
                int py = pix / 18, px = pix % 18;
                int gy = ty0 + py - 1, gx = tx0 + px - 1;
                float a = 0.f, b = 0.f;
                if (gy >= 0 && gy < HH && gx >= 0 && gx < WW) {
                    const float* base = in_f32 + gy * WW + gx;
                    a = base[(c0 + 2 * c2) * HW];
                    b = base[(c0 + 2 * c2 + 1) * HW];
                }
                __nv_bfloat16 ha = __float2bfloat16(a);
                __nv_bfloat16 hb = __float2bfloat16(b);
                __nv_bfloat16 la = __float2bfloat16(a - __bfloat162float(ha));
                __nv_bfloat16 lb = __float2bfloat16(b - __bfloat162float(hb));
                int h = c2 >> 2;
                int off = pix * 32 + ((h ^ ((pix >> 2) & 1)) << 4) + (c2 & 3) * 4;
                uint phi = ((uint)__bfloat16_as_ushort(hb) << 16) | __bfloat16_as_ushort(ha);
                uint plo = ((uint)__bfloat16_as_ushort(lb) << 16) | __bfloat16_as_ushort(la);
                *(uint*)(smem + SM_AHI + off) = phi;
                *(uint*)(smem + SM_ALO + off) = plo;
            }
        }
        for (int idx = tid; idx < 9 * 64 * 2; idx += 256) {
            int tap = idx / 128;
            int r = idx % 128;
            int oc = r >> 1, h = r & 1;
            long src = (long)(tap * OCPAD + ocb64 + oc) * Cin + c0 + h * 8;
            int dst = (tap * 64 + oc) * 32 + ((h ^ ((oc >> 2) & 1)) << 4);
            *(uint4*)(smem + SM_WHI + dst) = *(const uint4*)(whi + src);
            *(uint4*)(smem + SM_WLO + dst) = *(const uint4*)(wlo + src);
        }
        __syncthreads();

#pragma unroll
        for (int tap = 0; tap < 9; tap++) {
            const int dy = tap / 3, dx = tap % 3;
            uint ah[2][4], al[2][4];
#pragma unroll
            for (int mf = 0; mf < 2; mf++) {
                int m = warp * 32 + mf * 16 + r8;
                int pix = ((m >> 4) + dy) * 18 + (m & 15) + dx;
                uint off = pix * 32 + ((khalfA ^ ((pix >> 2) & 1)) << 4);
                ldsm_x4(ah[mf][0], ah[mf][1], ah[mf][2], ah[mf][3], smbase + SM_AHI + off);
                ldsm_x4(al[mf][0], al[mf][1], al[mf][2], al[mf][3], smbase + SM_ALO + off);
            }
#pragma unroll
            for (int nf = 0; nf < 8; nf++) {
                int oc8 = nf * 8 + oclane;
                uint boff = (uint)(tap * 64 + oc8) * 32 + ((matB ^ ((oc8 >> 2) & 1)) << 4);
                uint bh0, bh1, bl0, bl1;
                ldsm_x2(bh0, bh1, smbase + SM_WHI + boff);
                ldsm_x2(bl0, bl1, smbase + SM_WLO + boff);
#pragma unroll
                for (int mf = 0; mf < 2; mf++) {
                    mma_bf16(d[mf][nf], ah[mf], bh0, bh1);
                    mma_bf16(d[mf][nf], ah[mf], bl0, bl1);
                    mma_bf16(d[mf][nf], al[mf], bh0, bh1);
                }
            }
        }
    }

    const int groupID = lane >> 2, tig = lane & 3;
#pragma unroll
    for (int mf = 0; mf < 2; mf++) {
#pragma unroll
        for (int nf = 0; nf < 8; nf++) {
#pragma unroll
            for (int jj = 0; jj < 2; jj++) {
                int row = groupID + jj * 8;
                int m = warp * 32 + mf * 16 + row;
                int gy = ty0 + (m >> 4);
                int gx = tx0 + (m & 15);
                int oc0 = ocb64 + nf * 8 + 2 * tig;
                float v0 = d[mf][nf][jj * 2 + 0] + bias[min(oc0, Cout - 1)];
                float v1 = d[mf][nf][jj * 2 + 1] + bias[min(oc0 + 1, Cout - 1)];
                if (LRELU) {
                    v0 = v0 >= 0.f ? v0 : 0.1f * v0;
                    v1 = v1 >= 0.f ? v1 : 0.1f * v1;
                }
                if (BF16OUT) {
                    // Cout == OCPAD == 64 on this path
                    __nv_bfloat16 h0 = __float2bfloat16(v0);
                    __nv_bfloat16 h1 = __float2bfloat16(v1);
                    __nv_bfloat16 l0 = __float2bfloat16(v0 - __bfloat162float(h0));
                    __nv_bfloat16 l1 = __float2bfloat16(v1 - __bfloat162float(h1));
                    uint uh = ((uint)__bfloat16_as_ushort(h1) << 16) | __bfloat16_as_ushort(h0);
                    uint ul = ((uint)__bfloat16_as_ushort(l1) << 16) | __bfloat16_as_ushort(l0);
                    long base = (long)(gy * WW + gx) * 64 + oc0;
                    *(uint*)(out_hi + base) = uh;
                    *(uint*)(out_lo + base) = ul;
                } else {
                    if (oc0 < Cout)     out_f32[oc0 * HW + gy * WW + gx] = v0;
                    if (oc0 + 1 < Cout) out_f32[(oc0 + 1) * HW + gy * WW + gx] = v1;
                }
            }
        }
    }
}

// ---------------- fused deformable gather + grouped GEMM (NHWC feat) ----------------
__global__ __launch_bounds__(256, 2)
void dcn_fused_kernel(const float* __restrict__ featT,
                      const float* __restrict__ offraw,
                      const float* __restrict__ flow,
                      const float* __restrict__ w,
                      const float* __restrict__ bias,
                      float* __restrict__ out) {
    __shared__ __align__(8) float s_w[72][64];

    const int tid = threadIdx.x;
    const int px = blockIdx.x * 256 + tid;
    const int y = px >> 8, x = px & 255;

    const float fly = flow[HW + px], flx = flow[px];

    ull acc[32];
#pragma unroll
    for (int p = 0; p < 32; p++) acc[p] = 0ULL;

    for (int g = 0; g < 8; g++) {
        __syncthreads();
        for (int i = tid; i < 72 * 64; i += 256) {
            int oc = i & 63, ck = i >> 6;
            s_w[ck][oc] = w[oc * 576 + g * 72 + ck];
        }
        __syncthreads();

#pragma unroll
        for (int k = 0; k < 9; k++) {
            const int gk = g * 9 + k;
            float oy = 10.f * ftanh(offraw[(gk * 2 + 0) * HW + px]) + fly;
            float ox = 10.f * ftanh(offraw[(gk * 2 + 1) * HW + px]) + flx;
            float m = fsigmoid(offraw[(144 + gk) * HW + px]);

            float py = (float)y + (float)(k / 3 - 1) + oy;
            float pxx = (float)x + (float)(k % 3 - 1) + ox;
            float y0f = floorf(py), x0f = floorf(pxx);
            float ly = py - y0f, lx = pxx - x0f;
            int yi0 = (int)y0f, xi0 = (int)x0f;
            int yi1 = yi0 + 1, xi1 = xi0 + 1;
            float vy0 = (yi0 >= 0 && yi0 < HH) ? 1.f : 0.f;
            float vy1 = (yi1 >= 0 && yi1 < HH) ? 1.f : 0.f;
            float vx0 = (xi0 >= 0 && xi0 < WW) ? 1.f : 0.f;
            float vx1 = (xi1 >= 0 && xi1 < WW) ? 1.f : 0.f;
            int yc0 = min(max(yi0, 0), HH - 1), yc1 = min(max(yi1, 0), HH - 1);
            int xc0 = min(max(xi0, 0), WW - 1), xc1 = min(max(xi1, 0), WW - 1);
            float w00 = (1.f - ly) * (1.f - lx) * vy0 * vx0 * m;
            float w01 = (1.f - ly) * lx * vy0 * vx1 * m;
            float w10 = ly * (1.f - lx) * vy1 * vx0 * m;
            float w11 = ly * lx * vy1 * vx1 * m;

            const float* p00 = featT + (yc0 * WW + xc0) * 64 + g * 8;
            const float* p01 = featT + (yc0 * WW + xc1) * 64 + g * 8;
            const float* p10 = featT + (yc1 * WW + xc0) * 64 + g * 8;
            const float* p11 = featT + (yc1 * WW + xc1) * 64 + g * 8;

            float v[8];
#pragma unroll
            for (int h = 0; h < 2; h++) {
                float4 a00 = *(const float4*)(p00 + 4 * h);
                float4 a01 = *(const float4*)(p01 + 4 * h);
                float4 a10 = *(const float4*)(p10 + 4 * h);
                float4 a11 = *(const float4*)(p11 + 4 * h);
                v[4 * h + 0] = w00 * a00.x + w01 * a01.x + w10 * a10.x + w11 * a11.x;
                v[4 * h + 1] = w00 * a00.y + w01 * a01.y + w10 * a10.y + w11 * a11.y;
                v[4 * h + 2] = w00 * a00.z + w01 * a01.z + w10 * a10.z + w11 * a11.z;
                v[4 * h + 3] = w00 * a00.w + w01 * a01.w + w10 * a10.w + w11 * a11.w;
            }

#pragma unroll
            for (int c = 0; c < 8; c++) {
                ull sv;
                asm("mov.b64 %0, {%1, %1};" : "=l"(sv) : "f"(v[c]));
                const int row = c * 9 + k;
#pragma unroll
                for (int p = 0; p < 32; p++) {
                    ull wp = *reinterpret_cast<const ull*>(&s_w[row][2 * p]);
                    asm("fma.rn.f32x2 %0, %1, %2, %0;" : "+l"(acc[p]) : "l"(sv), "l"(wp));
                }
            }
        }
    }

#pragma unroll
    for (int p = 0; p < 32; p++) {
        int oc0 = 2 * p, oc1 = oc0 + 1;
        float a0, a1;
        asm("mov.b64 {%0, %1}, %2;" : "=f"(a0), "=f"(a1) : "l"(acc[p]));
        out[oc0 * HW + px] = a0 + bias[oc0];
        out[oc1 * HW + px] = a1 + bias[oc1];
    }
}

// ---------------- host side ----------------
extern "C" void kernel_launch(void* const* d_in, const int* in_sizes, int n_in,
                              void* d_out, int out_size) {
    const float* feat_prev  = (const float*)d_in[0];
    const float* feat_next  = (const float*)d_in[1];
    const float* extra_prev = (const float*)d_in[2];
    const float* extra_next = (const float*)d_in[3];
    const float* flow_prev  = (const float*)d_in[4];
    const float* flow_next  = (const float*)d_in[5];
    const float* dcn1_w = (const float*)d_in[22];
    const float* dcn1_b = (const float*)d_in[23];
    const float* dcn2_w = (const float*)d_in[24];
    const float* dcn2_b = (const float*)d_in[25];
    const float* fus_w  = (const float*)d_in[26];
    const float* fus_b  = (const float*)d_in[27];

    float *off, *cat, *featT;
    __nv_bfloat16 *whi, *wlo, *ehi, *elo, *ahi, *alo, *bhi, *blo;
    cudaGetSymbolAddress((void**)&off, g_off);
    cudaGetSymbolAddress((void**)&cat, g_cat);
    cudaGetSymbolAddress((void**)&featT, g_featT);
    cudaGetSymbolAddress((void**)&whi, g_whi);
    cudaGetSymbolAddress((void**)&wlo, g_wlo);
    cudaGetSymbolAddress((void**)&ehi, g_ext_hi);
    cudaGetSymbolAddress((void**)&elo, g_ext_lo);
    cudaGetSymbolAddress((void**)&ahi, g_a_hi);
    cudaGetSymbolAddress((void**)&alo, g_a_lo);
    cudaGetSymbolAddress((void**)&bhi, g_b_hi);
    cudaGetSymbolAddress((void**)&blo, g_b_lo);

    cudaFuncSetAttribute(conv_mma_kernel<true, true, true>,
                         cudaFuncAttributeMaxDynamicSharedMemorySize, SM_TOT);
    cudaFuncSetAttribute(conv_mma_kernel<false, true, false>,
                         cudaFuncAttributeMaxDynamicSharedMemorySize, SM_TOT);
    cudaFuncSetAttribute(conv_mma_kernel<false, false, false>,
                         cudaFuncAttributeMaxDynamicSharedMemorySize, SM_TOT);

    wconv_all_kernel<<<(W_TOTAL + 255) / 256, 256>>>(
        (const float*)d_in[6],  (const float*)d_in[8],  (const float*)d_in[10], (const float*)d_in[12],
        (const float*)d_in[14], (const float*)d_in[16], (const float*)d_in[18], (const float*)d_in[20],
        fus_w, whi, wlo);

    transpose_kernel<<<HW / 64, 256>>>(feat_prev, featT);
    transpose_kernel<<<HW / 64, 256>>>(feat_next, featT + 64 * HW);

    for (int br = 0; br < 2; br++) {
        const float* extra = br ? extra_next : extra_prev;
        const float* flow  = br ? flow_next  : flow_prev;
        const float* dw    = br ? dcn2_w : dcn1_w;
        const float* db    = br ? dcn2_b : dcn1_b;
        const __nv_bfloat16* bwhi = whi + br * BR_SZ;
        const __nv_bfloat16* bwlo = wlo + br * BR_SZ;
        const float* b0 = (const float*)d_in[br ? 15 : 7];
        const float* b1 = (const float*)d_in[br ? 17 : 9];
        const float* b2 = (const float*)d_in[br ? 19 : 11];
        const float* b3 = (const float*)d_in[br ? 21 : 13];

        split_transpose_kernel<<<HW / 64, 256>>>(extra, ehi, elo);

        dim3 g1(256, 1), g4(256, 4);
        conv_mma_kernel<true, true, true><<<g1, 256, SM_TOT>>>(
            nullptr, ehi, elo, bwhi + L0_OFF, bwlo + L0_OFF, b0,
            nullptr, ahi, alo, 128, 64, 64);
        conv_mma_kernel<true, true, true><<<g1, 256, SM_TOT>>>(
            nullptr, ahi, alo, bwhi + L1_OFF, bwlo + L1_OFF, b1,
            nullptr, bhi, blo, 64, 64, 64);
        conv_mma_kernel<true, true, true><<<g1, 256, SM_TOT>>>(
            nullptr, bhi, blo, bwhi + L2_OFF, bwlo + L2_OFF, b2,
            nullptr, ahi, alo, 64, 64, 64);
        conv_mma_kernel<false, true, false><<<g4, 256, SM_TOT>>>(
            nullptr, ahi, alo, bwhi + L3_OFF, bwlo + L3_OFF, b3,
            off, nullptr, nullptr, 64, 216, 256);

        dcn_fused_kernel<<<HW / 256, 256>>>(featT + br * 64 * HW, off, flow, dw, db,
                                            cat + br * 64 * HW);
    }

    conv_mma_kernel<false, false, false><<<dim3(256, 1), 256, SM_TOT>>>(
        cat, nullptr, nullptr, whi + FUS_OFF, wlo + FUS_OFF, fus_b,
        (float*)d_out, nullptr, nullptr, 128, 64, 64);
}